// round 9
// baseline (speedup 1.0000x reference)
#include <cuda_runtime.h>

#define NB 64
#define NS 512
#define NH 1024
#define NT 21
#define PF 4
#define FULLMASK 0xffffffffu

// Scratch: emissions [B, S, T] fp32 (2.75 MB)
__device__ float g_em[(size_t)NB * NS * NT];

__device__ __forceinline__ void fma2(unsigned long long& d, unsigned long long a,
                                     unsigned long long b) {
    asm("fma.rn.f32x2 %0, %1, %2, %0;" : "+l"(d) : "l"(a), "l"(b));
}

__device__ __forceinline__ float warpMaxF(float v) {
#pragma unroll
    for (int o = 16; o; o >>= 1) v = fmaxf(v, __shfl_xor_sync(FULLMASK, v, o));
    return v;
}
__device__ __forceinline__ float warpSumF(float v) {
#pragma unroll
    for (int o = 16; o; o >>= 1) v += __shfl_xor_sync(FULLMASK, v, o);
    return v;
}
__device__ __forceinline__ int warpSumI(int v) {
#pragma unroll
    for (int o = 16; o; o >>= 1) v += __shfl_xor_sync(FULLMASK, v, o);
    return v;
}

// depth-5 exact max tree over 21 register floats
__device__ __forceinline__ float fmax21(const float* v) {
    float a[11];
#pragma unroll
    for (int i = 0; i < 10; i++) a[i] = fmaxf(v[2 * i], v[2 * i + 1]);
    a[10] = v[20];
    float b[6];
#pragma unroll
    for (int i = 0; i < 5; i++) b[i] = fmaxf(a[2 * i], a[2 * i + 1]);
    b[5] = a[10];
    float c0 = fmaxf(b[0], b[1]), c1 = fmaxf(b[2], b[3]), c2 = fmaxf(b[4], b[5]);
    return fmaxf(fmaxf(c0, c1), c2);
}

// load 21 floats from a 32-float smem row (broadcast reads, conflict-free)
__device__ __forceinline__ void load21(const float* srow, float* e) {
    float4 f0 = *(const float4*)(srow + 0);
    float4 f1 = *(const float4*)(srow + 4);
    float4 f2 = *(const float4*)(srow + 8);
    float4 f3 = *(const float4*)(srow + 12);
    float4 f4 = *(const float4*)(srow + 16);
    e[0] = f0.x; e[1] = f0.y; e[2] = f0.z; e[3] = f0.w;
    e[4] = f1.x; e[5] = f1.y; e[6] = f1.z; e[7] = f1.w;
    e[8] = f2.x; e[9] = f2.y; e[10] = f2.z; e[11] = f2.w;
    e[12] = f3.x; e[13] = f3.y; e[14] = f3.z; e[15] = f3.w;
    e[16] = f4.x; e[17] = f4.y; e[18] = f4.z; e[19] = f4.w;
    e[20] = srow[20];
}

// ---------------------------------------------------------------------------
// Emissions: g_em[row][t] = dot(hs[row], W[t]) + b[t]
// 4-row register blocking; W staged in smem (84 KB).
// ---------------------------------------------------------------------------
extern __shared__ unsigned char s_raw[];

__global__ __launch_bounds__(256) void emissions_kernel(
    const float* __restrict__ hs, const float* __restrict__ W,
    const float* __restrict__ bias, float* __restrict__ out) {
    float* sW = (float*)s_raw;
    {
        const float4* src = (const float4*)W;
        float4* dst = (float4*)sW;
        for (int i = threadIdx.x; i < NT * NH / 4; i += blockDim.x) dst[i] = src[i];
    }
    if (blockIdx.x == 0 && threadIdx.x == 0) out[0] = 0.0f;  // zero loss accumulator
    __syncthreads();

    int q = threadIdx.x & 3;   // K sub-slice
    int g = threadIdx.x >> 2;  // row group 0..63
    int row0 = blockIdx.x * 256 + g * 4;

    unsigned long long acc[4][NT];
#pragma unroll
    for (int r = 0; r < 4; r++)
#pragma unroll
        for (int t = 0; t < NT; t++) acc[r][t] = 0ull;

    const ulonglong2* h0 = (const ulonglong2*)(hs + (size_t)row0 * NH);
    const ulonglong2* h1 = (const ulonglong2*)(hs + (size_t)(row0 + 1) * NH);
    const ulonglong2* h2 = (const ulonglong2*)(hs + (size_t)(row0 + 2) * NH);
    const ulonglong2* h3 = (const ulonglong2*)(hs + (size_t)(row0 + 3) * NH);
    const ulonglong2* wv = (const ulonglong2*)sW;  // tag row stride = NH/4 = 256

#pragma unroll 4
    for (int i = 0; i < 64; i++) {
        int idx = i * 4 + q;
        ulonglong2 a0 = h0[idx];
        ulonglong2 a1 = h1[idx];
        ulonglong2 a2 = h2[idx];
        ulonglong2 a3 = h3[idx];
#pragma unroll
        for (int t = 0; t < NT; t++) {
            ulonglong2 w = wv[t * 256 + idx];
            fma2(acc[0][t], a0.x, w.x);
            fma2(acc[0][t], a0.y, w.y);
            fma2(acc[1][t], a1.x, w.x);
            fma2(acc[1][t], a1.y, w.y);
            fma2(acc[2][t], a2.x, w.x);
            fma2(acc[2][t], a2.y, w.y);
            fma2(acc[3][t], a3.x, w.x);
            fma2(acc[3][t], a3.y, w.y);
        }
    }

#pragma unroll
    for (int t = 0; t < NT; t++) {
        float s[4];
#pragma unroll
        for (int r = 0; r < 4; r++) {
            float lo = __uint_as_float((unsigned)(acc[r][t] & 0xffffffffull));
            float hi = __uint_as_float((unsigned)(acc[r][t] >> 32));
            float v = lo + hi;
            v += __shfl_xor_sync(FULLMASK, v, 1);
            v += __shfl_xor_sync(FULLMASK, v, 2);
            s[r] = v;
        }
        g_em[(size_t)(row0 + q) * NT + t] = s[q] + bias[t];
    }
}

// ---------------------------------------------------------------------------
// CRF: one block per batch. One warp runs BOTH the forward recurrence and the
// Viterbi recurrence interleaved (independent chains -> ILP fills the stall
// slots of the lone warp). Shared emit/mask prefetch ring feeds both.
// ---------------------------------------------------------------------------
__global__ __launch_bounds__(32) void crf_kernel(
    const int* __restrict__ mask, const int* __restrict__ labels,
    const float* __restrict__ trans, const float* __restrict__ start,
    const float* __restrict__ endt, float* __restrict__ out) {
    int b = blockIdx.x;
    int lane = threadIdx.x;
    int jj = lane < NT ? lane : NT - 1;  // clamped for safe loads
    bool act = lane < NT;

    __shared__ float sV[2][2][32];  // [parity][chain][lane]
    __shared__ unsigned char bp[NS - 1][32];

    const float* em = g_em + (size_t)b * NS * NT;
    const int* mb = mask + (size_t)b * NS;

    // per-lane constants
    float ETc[NT], trc[NT];
#pragma unroll
    for (int i = 0; i < NT; i++) {
        float tr = trans[i * NT + jj];
        trc[i] = tr;
        ETc[i] = __expf(tr);
    }

    // ---- init both chains ----
    float em0 = em[jj];
    float alpha0 = start[jj] + em0;
    float a0 = act ? alpha0 : -1e30f;
    float m0 = warpMaxF(a0);
    float C = m0;
    float E = act ? __expf(alpha0 - m0) : 0.f;  // forward state (scaled)
    float sc = act ? alpha0 : -1e30f;           // viterbi state

    // shared prefetch rings
    float emr[PF], eem[PF];
    int mkr[PF];
#pragma unroll
    for (int k = 0; k < PF; k++) {
        float e = em[(1 + k) * NT + jj];
        emr[k] = e;
        eem[k] = __expf(e);
        mkr[k] = mb[1 + k];
    }

    auto step = [&](int t, int par) {
        float emit = emr[0];
        float eemc = eem[0];
        int mk = mkr[0];
#pragma unroll
        for (int k = 0; k < PF - 1; k++) {
            emr[k] = emr[k + 1];
            eem[k] = eem[k + 1];
            mkr[k] = mkr[k + 1];
        }
        int tn = t + PF;
        tn = tn < NS - 1 ? tn : NS - 1;  // clamp, no branch
        float etn = em[tn * NT + jj];
        emr[PF - 1] = etn;
        eem[PF - 1] = __expf(etn);
        mkr[PF - 1] = mb[tn];

        sV[par][0][lane] = E;
        sV[par][1][lane] = sc;
        __syncwarp();
        float e[NT], s[NT];
        load21(sV[par][0], e);
        load21(sV[par][1], s);

        // ---- forward chain ----
        float c0 = e[0] * ETc[0], c1 = e[1] * ETc[1], c2 = e[2] * ETc[2];
        float c3 = e[3] * ETc[3], c4 = e[4] * ETc[4], c5 = e[5] * ETc[5];
#pragma unroll
        for (int i = 6; i < NT; i++) {
            switch (i % 6) {
                case 0: c0 += e[i] * ETc[i]; break;
                case 1: c1 += e[i] * ETc[i]; break;
                case 2: c2 += e[i] * ETc[i]; break;
                case 3: c3 += e[i] * ETc[i]; break;
                case 4: c4 += e[i] * ETc[i]; break;
                default: c5 += e[i] * ETc[i]; break;
            }
        }
        float fs = ((c0 + c1) + (c2 + c3)) + (c4 + c5);
        E = mk ? fs * eemc : E;  // SEL (lanes>=21 garbage, never read)

        // ---- viterbi chain ----
        float v[NT];
#pragma unroll
        for (int i = 0; i < NT; i++) v[i] = s[i] + trc[i];
        float best = fmax21(v);  // exact max, loop-carried
        unsigned eqm = 0;        // exact first-occurrence argmax (off-path)
#pragma unroll
        for (int i = 0; i < NT; i++)
            if (v[i] == best) eqm |= (1u << i);
        int arg = __ffs(eqm) - 1;

        sc = mk ? best + emit : sc;                          // SEL
        bp[t - 1][lane] = (unsigned char)(mk ? arg : lane);  // SEL + STS
    };
    auto renorm = [&]() {
        float e0 = __shfl_sync(FULLMASK, E, 0);
        C += __logf(e0);
        E *= __fdividef(1.0f, e0);
    };

    // steps 1..7, renorm at t=7
#pragma unroll
    for (int k = 1; k <= 7; k++) step(k, k & 1);
    renorm();
    // 63 groups of 8 (t = 8g..8g+7), renorm at each group end (t&7==7)
    for (int g = 1; g < 64; g++) {
        int tb = g * 8;
#pragma unroll
        for (int k = 0; k < 8; k++) step(tb + k, k & 1);
        renorm();
    }
    __syncwarp();

    // ---- forward epilogue: logZ ----
    float term = act ? E * __expf(endt[jj]) : 0.f;
    float ssum = warpSumF(term);
    float logZ = C + __logf(ssum);

    // ---- viterbi epilogue: final argmax (lowest index on ties), exact ----
    float fv = act ? sc + endt[jj] : -1e30f;
    float fm = warpMaxF(fv);
    unsigned ball = __ballot_sync(FULLMASK, fv == fm);
    int idx = __ffs(ball) - 1;

    // ---- numerator (gold-path score) ----
    const int* lb = labels + (size_t)b * NS;
    float num = 0.f;
    int msum = 0;
    for (int t = lane; t < NS; t += 32) {
        int lt = lb[t];
        msum += mb[t];
        float e = em[t * NT + lt];
        if (t == 0)
            num += start[lt] + e;
        else
            num += (trans[lb[t - 1] * NT + lt] + e) * (float)mb[t];
    }
    num = warpSumF(num);
    msum = warpSumI(msum);

    if (lane == 0) {
        int last = lb[msum - 1];
        num += endt[last];
        atomicAdd(out, logZ - num);  // loss contribution

        // backtrace
        float* pred = out + 1 + (size_t)b * NS;
        int tag = idx;
        pred[NS - 1] = mb[NS - 1] ? (float)tag : 0.0f;
        for (int p = NS - 2; p >= 0; p--) {
            tag = bp[p][tag];
            pred[p] = mb[p] ? (float)tag : 0.0f;
        }
    }
}

// ---------------------------------------------------------------------------
extern "C" void kernel_launch(void* const* d_in, const int* in_sizes, int n_in,
                              void* d_out, int out_size) {
    const float* hs = (const float*)d_in[0];     // hidden_states [B,S,H] f32
    const int* mask = (const int*)d_in[1];       // attention_mask [B,S] i32
    const int* labels = (const int*)d_in[2];     // labels [B,S] i32
    const float* W = (const float*)d_in[3];      // [T,H]
    const float* bias = (const float*)d_in[4];   // [T]
    const float* trans = (const float*)d_in[5];  // [T,T]
    const float* start = (const float*)d_in[6];  // [T]
    const float* endt = (const float*)d_in[7];   // [T]
    float* out = (float*)d_out;                  // [1 + B*S] f32

    cudaFuncSetAttribute(emissions_kernel,
                         cudaFuncAttributeMaxDynamicSharedMemorySize,
                         NT * NH * (int)sizeof(float));

    emissions_kernel<<<(NB * NS) / 256, 256, NT * NH * sizeof(float)>>>(hs, W, bias, out);
    crf_kernel<<<NB, 32>>>(mask, labels, trans, start, endt, out);
}

// round 10
// speedup vs baseline: 1.1332x; 1.1332x over previous
#include <cuda_runtime.h>

#define NB 64
#define NS 512
#define NH 1024
#define NT 21
#define PF 4
#define FULLMASK 0xffffffffu

// Scratch: emissions [B, S, T] fp32 (2.75 MB)
__device__ float g_em[(size_t)NB * NS * NT];

__device__ __forceinline__ void fma2(unsigned long long& d, unsigned long long a,
                                     unsigned long long b) {
    asm("fma.rn.f32x2 %0, %1, %2, %0;" : "+l"(d) : "l"(a), "l"(b));
}
__device__ __forceinline__ unsigned long long add2(unsigned long long a,
                                                   unsigned long long b) {
    unsigned long long d;
    asm("add.rn.f32x2 %0, %1, %2;" : "=l"(d) : "l"(a), "l"(b));
    return d;
}
__device__ __forceinline__ unsigned long long pack2(float lo, float hi) {
    unsigned long long d;
    asm("mov.b64 %0, {%1, %2};" : "=l"(d) : "f"(lo), "f"(hi));
    return d;
}
__device__ __forceinline__ void unpack2(unsigned long long v, float& lo, float& hi) {
    asm("mov.b64 {%0, %1}, %2;" : "=f"(lo), "=f"(hi) : "l"(v));
}

__device__ __forceinline__ float warpMaxF(float v) {
#pragma unroll
    for (int o = 16; o; o >>= 1) v = fmaxf(v, __shfl_xor_sync(FULLMASK, v, o));
    return v;
}
__device__ __forceinline__ float warpSumF(float v) {
#pragma unroll
    for (int o = 16; o; o >>= 1) v += __shfl_xor_sync(FULLMASK, v, o);
    return v;
}
__device__ __forceinline__ int warpSumI(int v) {
#pragma unroll
    for (int o = 16; o; o >>= 1) v += __shfl_xor_sync(FULLMASK, v, o);
    return v;
}

// depth-5 exact max tree over 21 register floats
__device__ __forceinline__ float fmax21(const float* v) {
    float a[11];
#pragma unroll
    for (int i = 0; i < 10; i++) a[i] = fmaxf(v[2 * i], v[2 * i + 1]);
    a[10] = v[20];
    float b[6];
#pragma unroll
    for (int i = 0; i < 5; i++) b[i] = fmaxf(a[2 * i], a[2 * i + 1]);
    b[5] = a[10];
    float c0 = fmaxf(b[0], b[1]), c1 = fmaxf(b[2], b[3]), c2 = fmaxf(b[4], b[5]);
    return fmaxf(fmaxf(c0, c1), c2);
}

// ---------------------------------------------------------------------------
// Emissions: g_em[row][t] = dot(hs[row], W[t]) + b[t]   (unchanged from R9)
// ---------------------------------------------------------------------------
extern __shared__ unsigned char s_raw[];

__global__ __launch_bounds__(256) void emissions_kernel(
    const float* __restrict__ hs, const float* __restrict__ W,
    const float* __restrict__ bias, float* __restrict__ out) {
    float* sW = (float*)s_raw;
    {
        const float4* src = (const float4*)W;
        float4* dst = (float4*)sW;
        for (int i = threadIdx.x; i < NT * NH / 4; i += blockDim.x) dst[i] = src[i];
    }
    if (blockIdx.x == 0 && threadIdx.x == 0) out[0] = 0.0f;  // zero loss accumulator
    __syncthreads();

    int q = threadIdx.x & 3;   // K sub-slice
    int g = threadIdx.x >> 2;  // row group 0..63
    int row0 = blockIdx.x * 256 + g * 4;

    unsigned long long acc[4][NT];
#pragma unroll
    for (int r = 0; r < 4; r++)
#pragma unroll
        for (int t = 0; t < NT; t++) acc[r][t] = 0ull;

    const ulonglong2* h0 = (const ulonglong2*)(hs + (size_t)row0 * NH);
    const ulonglong2* h1 = (const ulonglong2*)(hs + (size_t)(row0 + 1) * NH);
    const ulonglong2* h2 = (const ulonglong2*)(hs + (size_t)(row0 + 2) * NH);
    const ulonglong2* h3 = (const ulonglong2*)(hs + (size_t)(row0 + 3) * NH);
    const ulonglong2* wv = (const ulonglong2*)sW;  // tag row stride = NH/4 = 256

#pragma unroll 4
    for (int i = 0; i < 64; i++) {
        int idx = i * 4 + q;
        ulonglong2 a0 = h0[idx];
        ulonglong2 a1 = h1[idx];
        ulonglong2 a2 = h2[idx];
        ulonglong2 a3 = h3[idx];
#pragma unroll
        for (int t = 0; t < NT; t++) {
            ulonglong2 w = wv[t * 256 + idx];
            fma2(acc[0][t], a0.x, w.x);
            fma2(acc[0][t], a0.y, w.y);
            fma2(acc[1][t], a1.x, w.x);
            fma2(acc[1][t], a1.y, w.y);
            fma2(acc[2][t], a2.x, w.x);
            fma2(acc[2][t], a2.y, w.y);
            fma2(acc[3][t], a3.x, w.x);
            fma2(acc[3][t], a3.y, w.y);
        }
    }

#pragma unroll
    for (int t = 0; t < NT; t++) {
        float s[4];
#pragma unroll
        for (int r = 0; r < 4; r++) {
            float lo, hi;
            unpack2(acc[r][t], lo, hi);
            float v = lo + hi;
            v += __shfl_xor_sync(FULLMASK, v, 1);
            v += __shfl_xor_sync(FULLMASK, v, 2);
            s[r] = v;
        }
        g_em[(size_t)(row0 + q) * NT + t] = s[q] + bias[t];
    }
}

// ---------------------------------------------------------------------------
// CRF: blocks 0..63 = forward (logZ + numerator -> loss), 64..127 = Viterbi.
// One warp per batch, lane j = state j. Branchless bodies, packed f32x2 math.
// ---------------------------------------------------------------------------
__global__ __launch_bounds__(32) void crf_kernel(
    const int* __restrict__ mask, const int* __restrict__ labels,
    const float* __restrict__ trans, const float* __restrict__ start,
    const float* __restrict__ endt, float* __restrict__ out) {
    int b = blockIdx.x & (NB - 1);
    int mode = blockIdx.x >> 6;
    int lane = threadIdx.x;
    int jj = lane < NT ? lane : NT - 1;  // clamped for safe loads
    bool act = lane < NT;

    __shared__ __align__(16) float sV[2][32];  // double-buffered broadcast row

    const float* em = g_em + (size_t)b * NS * NT;
    const int* mb = mask + (size_t)b * NS;

    if (mode == 0) {
        // ---------------- Forward algorithm (scaled domain) ----------------
        unsigned long long ETp[10];  // packed exp(trans) pairs
        float ETc20;
#pragma unroll
        for (int i = 0; i < 10; i++)
            ETp[i] = pack2(__expf(trans[(2 * i) * NT + jj]),
                           __expf(trans[(2 * i + 1) * NT + jj]));
        ETc20 = __expf(trans[20 * NT + jj]);

        float alpha0 = start[jj] + em[jj];
        float a0 = act ? alpha0 : -1e30f;
        float m0 = warpMaxF(a0);
        float C = m0;
        float E = act ? __expf(alpha0 - m0) : 0.f;

        float eem[PF];
        int mkr[PF];
#pragma unroll
        for (int k = 0; k < PF; k++) {
            eem[k] = __expf(em[(1 + k) * NT + jj]);
            mkr[k] = mb[1 + k];
        }

        auto fwd_step = [&](int t, int par) {
            float eemc = eem[0];
            int mk = mkr[0];
#pragma unroll
            for (int k = 0; k < PF - 1; k++) {
                eem[k] = eem[k + 1];
                mkr[k] = mkr[k + 1];
            }
            int tn = t + PF;
            tn = tn < NS - 1 ? tn : NS - 1;  // clamp, no branch
            eem[PF - 1] = __expf(em[tn * NT + jj]);
            mkr[PF - 1] = mb[tn];

            sV[par][lane] = E;
            __syncwarp();
            const ulonglong2* sp = (const ulonglong2*)sV[par];
            ulonglong2 p0 = sp[0], p1 = sp[1], p2 = sp[2], p3 = sp[3], p4 = sp[4];
            float e20 = sV[par][20];

            unsigned long long a0 = 0ull, a1 = 0ull, a2 = 0ull, a3 = 0ull;
            fma2(a0, p0.x, ETp[0]);
            fma2(a1, p0.y, ETp[1]);
            fma2(a2, p1.x, ETp[2]);
            fma2(a3, p1.y, ETp[3]);
            fma2(a0, p2.x, ETp[4]);
            fma2(a1, p2.y, ETp[5]);
            fma2(a2, p3.x, ETp[6]);
            fma2(a3, p3.y, ETp[7]);
            fma2(a0, p4.x, ETp[8]);
            fma2(a1, p4.y, ETp[9]);

            float l0, h0f, l1, h1f, l2, h2f, l3, h3f;
            unpack2(a0, l0, h0f);
            unpack2(a1, l1, h1f);
            unpack2(a2, l2, h2f);
            unpack2(a3, l3, h3f);
            float s = ((l0 + h0f) + (l1 + h1f)) + ((l2 + h2f) + (l3 + h3f));
            s = fmaf(e20, ETc20, s);
            E = mk ? s * eemc : E;  // SEL (lanes>=21 garbage, never read)
        };
        auto renorm = [&]() {
            float e0 = __shfl_sync(FULLMASK, E, 0);
            C += __logf(e0);
            E *= __fdividef(1.0f, e0);
        };

#pragma unroll
        for (int k = 1; k <= 7; k++) fwd_step(k, k & 1);
        renorm();
        for (int g = 1; g < 64; g++) {
            int tb = g * 8;
#pragma unroll
            for (int k = 0; k < 8; k++) fwd_step(tb + k, k & 1);
            renorm();
        }

        float term = act ? E * __expf(endt[jj]) : 0.f;
        float ssum = warpSumF(term);
        float logZ = C + __logf(ssum);

        // ---------------- Numerator (gold-path score) ----------------
        const int* lb = labels + (size_t)b * NS;
        float num = 0.f;
        int msum = 0;
        for (int t = lane; t < NS; t += 32) {
            int lt = lb[t];
            msum += mb[t];
            float e = em[t * NT + lt];
            if (t == 0)
                num += start[lt] + e;
            else
                num += (trans[lb[t - 1] * NT + lt] + e) * (float)mb[t];
        }
        num = warpSumF(num);
        msum = warpSumI(msum);
        if (lane == 0) {
            int last = lb[msum - 1];
            num += endt[last];
            atomicAdd(out, logZ - num);  // loss contribution
        }
    } else {
        // ---------------- Viterbi ----------------
        __shared__ unsigned char bp[NS - 1][32];
        unsigned long long trp[10];  // packed trans pairs
        float trc20 = trans[20 * NT + jj];
#pragma unroll
        for (int i = 0; i < 10; i++)
            trp[i] = pack2(trans[(2 * i) * NT + jj], trans[(2 * i + 1) * NT + jj]);

        float sc = act ? start[jj] + em[jj] : -1e30f;

        float emr[PF];
        int mkr[PF];
#pragma unroll
        for (int k = 0; k < PF; k++) {
            emr[k] = em[(1 + k) * NT + jj];
            mkr[k] = mb[1 + k];
        }

        auto vit_step = [&](int t, int par) {
            float emit = emr[0];
            int mk = mkr[0];
#pragma unroll
            for (int k = 0; k < PF - 1; k++) {
                emr[k] = emr[k + 1];
                mkr[k] = mkr[k + 1];
            }
            int tn = t + PF;
            tn = tn < NS - 1 ? tn : NS - 1;
            emr[PF - 1] = em[tn * NT + jj];
            mkr[PF - 1] = mb[tn];

            sV[par][lane] = sc;
            __syncwarp();
            const ulonglong2* sp = (const ulonglong2*)sV[par];
            ulonglong2 p0 = sp[0], p1 = sp[1], p2 = sp[2], p3 = sp[3], p4 = sp[4];
            float s20 = sV[par][20];

            unsigned long long vp[10];
            vp[0] = add2(p0.x, trp[0]);
            vp[1] = add2(p0.y, trp[1]);
            vp[2] = add2(p1.x, trp[2]);
            vp[3] = add2(p1.y, trp[3]);
            vp[4] = add2(p2.x, trp[4]);
            vp[5] = add2(p2.y, trp[5]);
            vp[6] = add2(p3.x, trp[6]);
            vp[7] = add2(p3.y, trp[7]);
            vp[8] = add2(p4.x, trp[8]);
            vp[9] = add2(p4.y, trp[9]);

            float v[NT];
#pragma unroll
            for (int i = 0; i < 10; i++) unpack2(vp[i], v[2 * i], v[2 * i + 1]);
            v[20] = s20 + trc20;

            float best = fmax21(v);  // exact max, loop-carried
            unsigned eqm = 0;        // exact first-occurrence argmax (off-path)
#pragma unroll
            for (int i = 0; i < NT; i++)
                if (v[i] == best) eqm |= (1u << i);
            int arg = __ffs(eqm) - 1;

            sc = mk ? best + emit : sc;                          // SEL
            bp[t - 1][lane] = (unsigned char)(mk ? arg : lane);  // SEL + STS
        };

#pragma unroll
        for (int k = 1; k <= 7; k++) vit_step(k, k & 1);
        for (int g = 1; g < 64; g++) {
            int tb = g * 8;
#pragma unroll
            for (int k = 0; k < 8; k++) vit_step(tb + k, k & 1);
        }
        __syncwarp();

        // argmax over final score + end (lowest index on ties), exact
        float fv = act ? sc + endt[jj] : -1e30f;
        float fm = warpMaxF(fv);
        unsigned ball = __ballot_sync(FULLMASK, fv == fm);
        int idx = __ffs(ball) - 1;

        if (lane == 0) {
            float* pred = out + 1 + (size_t)b * NS;
            int tag = idx;
            pred[NS - 1] = mb[NS - 1] ? (float)tag : 0.0f;
            for (int p = NS - 2; p >= 0; p--) {
                tag = bp[p][tag];
                pred[p] = mb[p] ? (float)tag : 0.0f;
            }
        }
    }
}

// ---------------------------------------------------------------------------
extern "C" void kernel_launch(void* const* d_in, const int* in_sizes, int n_in,
                              void* d_out, int out_size) {
    const float* hs = (const float*)d_in[0];     // hidden_states [B,S,H] f32
    const int* mask = (const int*)d_in[1];       // attention_mask [B,S] i32
    const int* labels = (const int*)d_in[2];     // labels [B,S] i32
    const float* W = (const float*)d_in[3];      // [T,H]
    const float* bias = (const float*)d_in[4];   // [T]
    const float* trans = (const float*)d_in[5];  // [T,T]
    const float* start = (const float*)d_in[6];  // [T]
    const float* endt = (const float*)d_in[7];   // [T]
    float* out = (float*)d_out;                  // [1 + B*S] f32

    cudaFuncSetAttribute(emissions_kernel,
                         cudaFuncAttributeMaxDynamicSharedMemorySize,
                         NT * NH * (int)sizeof(float));

    emissions_kernel<<<(NB * NS) / 256, 256, NT * NH * sizeof(float)>>>(hs, W, bias, out);
    crf_kernel<<<2 * NB, 32>>>(mask, labels, trans, start, endt, out);
}